// round 1
// baseline (speedup 1.0000x reference)
#include <cuda_runtime.h>
#include <math.h>

#define NN 200000
#define NE 400000
#define HD 128

// ---------------- scratch (static device memory; no allocs allowed) ----------
__device__ float g_agg[(size_t)NN * 64];
__device__ float g_xcA[(size_t)NN * HD];
__device__ float g_xcB[(size_t)NN * HD];

__device__ __forceinline__ float4 ld4(const float* p) { return *reinterpret_cast<const float4*>(p); }
__device__ __forceinline__ void st4(float* p, float4 v) { *reinterpret_cast<float4*>(p) = v; }

// packed f32x2 fma: d = a*b + d (lanewise on 2 packed floats)
__device__ __forceinline__ void fma2(unsigned long long& d, unsigned long long a, unsigned long long b) {
    asm("fma.rn.f32x2 %0, %1, %2, %0;" : "+l"(d) : "l"(a), "l"(b));
}
__device__ __forceinline__ unsigned long long bcast2(float a) {
    unsigned long long r;
    asm("mov.b64 %0, {%1, %1};" : "=l"(r) : "f"(a));
    return r;
}
__device__ __forceinline__ void unpack2(unsigned long long v, float& lo, float& hi) {
    asm("mov.b64 {%0, %1}, %2;" : "=f"(lo), "=f"(hi) : "l"(v));
}

// ---------------- zero + scatter ---------------------------------------------
__global__ void zero_agg_kernel() {
    size_t n = (size_t)NN * 64 / 4;
    for (size_t i = (size_t)blockIdx.x * blockDim.x + threadIdx.x; i < n;
         i += (size_t)gridDim.x * blockDim.x)
        reinterpret_cast<float4*>(g_agg)[i] = make_float4(0.f, 0.f, 0.f, 0.f);
}

// agg[n][c] = sum_{e: rcv==n} ea[e][c] + sum_{e: snd==n} ea[e][c+64]
__global__ void __launch_bounds__(256) scatter_kernel(
    const float* __restrict__ ea, const int* __restrict__ snd, const int* __restrict__ rcv)
{
    long t = (long)blockIdx.x * blockDim.x + threadIdx.x;
    if (t >= (long)NE * 128) return;
    int e = (int)(t >> 7);
    int c = (int)(t & 127);
    float v = ea[t];
    if (c < 64) atomicAdd(&g_agg[(size_t)rcv[e] * 64 + c], v);
    else        atomicAdd(&g_agg[(size_t)snd[e] * 64 + (c - 64)], v);
}

// ---------------- shared GEMM pieces -----------------------------------------
// CTA tile: 64 rows x 128 cols, 256 threads. warp = ty (0..7) owns rows
// [ty*8, ty*8+8); lane = tx (0..31) owns cols [tx*4, tx*4+4).
// acc held as f32x2 pairs: acc2[i][0] = cols (c, c+1), acc2[i][1] = (c+2, c+3).

// GEMM over K=128 where A is resident in smem (act_in), W streamed via w_tile.
__device__ __forceinline__ void gemm128_smem(
    const float* __restrict__ wmat, float* w_tile, const float* act_in,
    unsigned long long acc2[8][2], int ty, int tx)
{
    for (int kt = 0; kt < 128; kt += 32) {
#pragma unroll
        for (int q = 0; q < 4; q++) {
            int idx = threadIdx.x + q * 256;
            int k = idx >> 5, c4 = (idx & 31) * 4;
            st4(&w_tile[k * 128 + c4], ld4(&wmat[(size_t)(kt + k) * 128 + c4]));
        }
        __syncthreads();
#pragma unroll
        for (int k = 0; k < 32; k++) {
            double2 wv = *reinterpret_cast<const double2*>(&w_tile[k * 128 + tx * 4]);
            unsigned long long w01 = __double_as_longlong(wv.x);
            unsigned long long w23 = __double_as_longlong(wv.y);
#pragma unroll
            for (int i = 0; i < 8; i++) {
                unsigned long long a2 = bcast2(act_in[(ty * 8 + i) * 128 + kt + k]);
                fma2(acc2[i][0], a2, w01);
                fma2(acc2[i][1], a2, w23);
            }
        }
        __syncthreads();
    }
}

__device__ __forceinline__ void silu_store(
    unsigned long long acc2[8][2], const float* __restrict__ b, float* actout, int ty, int tx)
{
    int c = tx * 4;
    float b0 = b[c], b1 = b[c + 1], b2 = b[c + 2], b3 = b[c + 3];
#pragma unroll
    for (int i = 0; i < 8; i++) {
        float v0, v1, v2, v3;
        unpack2(acc2[i][0], v0, v1);
        unpack2(acc2[i][1], v2, v3);
        v0 += b0; v1 += b1; v2 += b2; v3 += b3;
        float4 o;
        o.x = v0 / (1.f + expf(-v0));
        o.y = v1 / (1.f + expf(-v1));
        o.z = v2 / (1.f + expf(-v2));
        o.w = v3 / (1.f + expf(-v3));
        st4(&actout[(ty * 8 + i) * 128 + c], o);
    }
}

// bias + LayerNorm + optional raw output (out1) + optional residual output (resid+out2)
__device__ __forceinline__ void ln_out(
    unsigned long long acc2[8][2], const float* __restrict__ b3,
    const float* __restrict__ gam, const float* __restrict__ beta,
    float* __restrict__ out1, const float* __restrict__ resid, float* __restrict__ out2,
    int row0, int ty, int tx)
{
    int c = tx * 4;
    float bb0 = b3[c], bb1 = b3[c + 1], bb2 = b3[c + 2], bb3 = b3[c + 3];
    float g0 = gam[c], g1 = gam[c + 1], g2 = gam[c + 2], g3 = gam[c + 3];
    float be0 = beta[c], be1 = beta[c + 1], be2 = beta[c + 2], be3 = beta[c + 3];
#pragma unroll
    for (int i = 0; i < 8; i++) {
        int r = row0 + ty * 8 + i;
        float v0, v1, v2, v3;
        unpack2(acc2[i][0], v0, v1);
        unpack2(acc2[i][1], v2, v3);
        v0 += bb0; v1 += bb1; v2 += bb2; v3 += bb3;
        float s = v0 + v1 + v2 + v3;
        float s2 = v0 * v0 + v1 * v1 + v2 * v2 + v3 * v3;
#pragma unroll
        for (int off = 16; off > 0; off >>= 1) {
            s  += __shfl_xor_sync(0xffffffffu, s,  off);
            s2 += __shfl_xor_sync(0xffffffffu, s2, off);
        }
        float mean = s * (1.f / 128.f);
        float var = s2 * (1.f / 128.f) - mean * mean;
        float rstd = rsqrtf(var + 1e-5f);
        float4 o;
        o.x = (v0 - mean) * rstd * g0 + be0;
        o.y = (v1 - mean) * rstd * g1 + be1;
        o.z = (v2 - mean) * rstd * g2 + be2;
        o.w = (v3 - mean) * rstd * g3 + be3;
        if (out1) st4(&out1[(size_t)r * 128 + c], o);
        if (out2) {
            float4 rv = ld4(&resid[(size_t)r * 128 + c]);
            o.x += rv.x; o.y += rv.y; o.z += rv.z; o.w += rv.w;
            st4(&out2[(size_t)r * 128 + c], o);
        }
    }
}

// ---------------- cell (node) MLP: in = [xc(128), agg(64)] -> 128 ------------
__global__ void __launch_bounds__(256) cell_mlp_kernel(
    const float* __restrict__ xin,
    const float* __restrict__ w1, const float* __restrict__ b1,
    const float* __restrict__ w2, const float* __restrict__ b2,
    const float* __restrict__ w3, const float* __restrict__ b3,
    const float* __restrict__ gam, const float* __restrict__ beta,
    float* __restrict__ xc_out, const float* __restrict__ resid, float* __restrict__ out2)
{
    extern __shared__ float smem[];
    float* a_tile = smem;                 // 64*32
    float* w_tile = smem + 2048;          // 32*128
    float* act0 = w_tile + 4096;          // 64*128
    float* act1 = act0 + 8192;            // 64*128

    int ty = threadIdx.x >> 5, tx = threadIdx.x & 31;
    int row0 = blockIdx.x * 64;

    unsigned long long acc2[8][2];
#pragma unroll
    for (int i = 0; i < 8; i++) { acc2[i][0] = 0ull; acc2[i][1] = 0ull; }

    // GEMM1: K = 192  (cols 0-127 from xin, 128-191 from g_agg)
    for (int kt = 0; kt < 192; kt += 32) {
#pragma unroll
        for (int q = 0; q < 2; q++) {
            int idx = threadIdx.x + q * 256;
            int r = idx >> 3, kq = (idx & 7) * 4;
            int kk = kt + kq;
            float4 v = (kk < 128)
                ? ld4(&xin[(size_t)(row0 + r) * 128 + kk])
                : ld4(&g_agg[(size_t)(row0 + r) * 64 + (kk - 128)]);
            st4(&a_tile[r * 32 + kq], v);
        }
#pragma unroll
        for (int q = 0; q < 4; q++) {
            int idx = threadIdx.x + q * 256;
            int k = idx >> 5, c4 = (idx & 31) * 4;
            st4(&w_tile[k * 128 + c4], ld4(&w1[(size_t)(kt + k) * 128 + c4]));
        }
        __syncthreads();
#pragma unroll
        for (int k = 0; k < 32; k++) {
            double2 wv = *reinterpret_cast<const double2*>(&w_tile[k * 128 + tx * 4]);
            unsigned long long w01 = __double_as_longlong(wv.x);
            unsigned long long w23 = __double_as_longlong(wv.y);
#pragma unroll
            for (int i = 0; i < 8; i++) {
                unsigned long long a2 = bcast2(a_tile[(ty * 8 + i) * 32 + k]);
                fma2(acc2[i][0], a2, w01);
                fma2(acc2[i][1], a2, w23);
            }
        }
        __syncthreads();
    }
    silu_store(acc2, b1, act0, ty, tx);
    __syncthreads();

#pragma unroll
    for (int i = 0; i < 8; i++) { acc2[i][0] = 0ull; acc2[i][1] = 0ull; }
    gemm128_smem(w2, w_tile, act0, acc2, ty, tx);
    silu_store(acc2, b2, act1, ty, tx);
    __syncthreads();

#pragma unroll
    for (int i = 0; i < 8; i++) { acc2[i][0] = 0ull; acc2[i][1] = 0ull; }
    gemm128_smem(w3, w_tile, act1, acc2, ty, tx);
    ln_out(acc2, b3, gam, beta, xc_out, resid, out2, row0, ty, tx);
}

// ---------------- edge MLP: in = [ea(128), xc[s](128), xc[r](128)] -> 128 ----
__global__ void __launch_bounds__(256) edge_mlp_kernel(
    const float* __restrict__ ea, const float* __restrict__ xc,
    const int* __restrict__ snd, const int* __restrict__ rcv,
    const float* __restrict__ w1, const float* __restrict__ b1,
    const float* __restrict__ w2, const float* __restrict__ b2,
    const float* __restrict__ w3, const float* __restrict__ b3,
    const float* __restrict__ gam, const float* __restrict__ beta,
    float* __restrict__ out2)
{
    extern __shared__ float smem[];
    float* a_tile = smem;
    float* w_tile = smem + 2048;
    float* act0 = w_tile + 4096;
    float* act1 = act0 + 8192;
    int* sidx = (int*)(act1 + 8192);      // 64 senders then 64 receivers

    int ty = threadIdx.x >> 5, tx = threadIdx.x & 31;
    int row0 = blockIdx.x * 64;

    if (threadIdx.x < 64) sidx[threadIdx.x] = snd[row0 + threadIdx.x];
    else if (threadIdx.x < 128) sidx[threadIdx.x] = rcv[row0 + threadIdx.x - 64];
    __syncthreads();

    unsigned long long acc2[8][2];
#pragma unroll
    for (int i = 0; i < 8; i++) { acc2[i][0] = 0ull; acc2[i][1] = 0ull; }

    // GEMM1: K = 384
    for (int kt = 0; kt < 384; kt += 32) {
#pragma unroll
        for (int q = 0; q < 2; q++) {
            int idx = threadIdx.x + q * 256;
            int r = idx >> 3, kq = (idx & 7) * 4;
            int kk = kt + kq;
            const float* p;
            if (kk < 128)      p = &ea[(size_t)(row0 + r) * 128 + kk];
            else if (kk < 256) p = &xc[(size_t)sidx[r] * 128 + (kk - 128)];
            else               p = &xc[(size_t)sidx[64 + r] * 128 + (kk - 256)];
            st4(&a_tile[r * 32 + kq], ld4(p));
        }
#pragma unroll
        for (int q = 0; q < 4; q++) {
            int idx = threadIdx.x + q * 256;
            int k = idx >> 5, c4 = (idx & 31) * 4;
            st4(&w_tile[k * 128 + c4], ld4(&w1[(size_t)(kt + k) * 128 + c4]));
        }
        __syncthreads();
#pragma unroll
        for (int k = 0; k < 32; k++) {
            double2 wv = *reinterpret_cast<const double2*>(&w_tile[k * 128 + tx * 4]);
            unsigned long long w01 = __double_as_longlong(wv.x);
            unsigned long long w23 = __double_as_longlong(wv.y);
#pragma unroll
            for (int i = 0; i < 8; i++) {
                unsigned long long a2 = bcast2(a_tile[(ty * 8 + i) * 32 + k]);
                fma2(acc2[i][0], a2, w01);
                fma2(acc2[i][1], a2, w23);
            }
        }
        __syncthreads();
    }
    silu_store(acc2, b1, act0, ty, tx);
    __syncthreads();

#pragma unroll
    for (int i = 0; i < 8; i++) { acc2[i][0] = 0ull; acc2[i][1] = 0ull; }
    gemm128_smem(w2, w_tile, act0, acc2, ty, tx);
    silu_store(acc2, b2, act1, ty, tx);
    __syncthreads();

#pragma unroll
    for (int i = 0; i < 8; i++) { acc2[i][0] = 0ull; acc2[i][1] = 0ull; }
    gemm128_smem(w3, w_tile, act1, acc2, ty, tx);
    // e_out = e0 + LN(h3);  no raw output needed
    ln_out(acc2, b3, gam, beta, nullptr, ea, out2, row0, ty, tx);
}

// ---------------- launch -----------------------------------------------------
#define SMEM_CELL ((2048 + 4096 + 8192 + 8192) * 4)
#define SMEM_EDGE (SMEM_CELL + 128 * 4)

extern "C" void kernel_launch(void* const* d_in, const int* in_sizes, int n_in,
                              void* d_out, int out_size)
{
    const float* x       = (const float*)d_in[0];
    const float* ea      = (const float*)d_in[1];
    const float* cb_w1   = (const float*)d_in[2];
    const float* cb_b1   = (const float*)d_in[3];
    const float* cb_w2   = (const float*)d_in[4];
    const float* cb_b2   = (const float*)d_in[5];
    const float* cb_w3   = (const float*)d_in[6];
    const float* cb_b3   = (const float*)d_in[7];
    const float* cb_g    = (const float*)d_in[8];
    const float* cb_beta = (const float*)d_in[9];
    const float* eb_w1   = (const float*)d_in[10];
    const float* eb_b1   = (const float*)d_in[11];
    const float* eb_w2   = (const float*)d_in[12];
    const float* eb_b2   = (const float*)d_in[13];
    const float* eb_w3   = (const float*)d_in[14];
    const float* eb_b3   = (const float*)d_in[15];
    const float* eb_g    = (const float*)d_in[16];
    const float* eb_beta = (const float*)d_in[17];
    const int*   ei      = (const int*)d_in[18];
    const int* snd = ei;
    const int* rcv = ei + NE;

    float* out_x = (float*)d_out;
    float* out_e = out_x + (size_t)NN * HD;

    float *xcA, *xcB;
    cudaGetSymbolAddress((void**)&xcA, g_xcA);
    cudaGetSymbolAddress((void**)&xcB, g_xcB);

    cudaFuncSetAttribute(cell_mlp_kernel, cudaFuncAttributeMaxDynamicSharedMemorySize, SMEM_CELL);
    cudaFuncSetAttribute(edge_mlp_kernel, cudaFuncAttributeMaxDynamicSharedMemorySize, SMEM_EDGE);

    // 1) agg = scatter(edge_attr)  — loop-invariant, computed once
    zero_agg_kernel<<<2048, 256>>>();
    scatter_kernel<<<(int)(((long)NE * 128 + 255) / 256), 256>>>(ea, snd, rcv);

    // 2) two rounds of cell MLP (shared weights, same agg)
    cell_mlp_kernel<<<NN / 64, 256, SMEM_CELL>>>(
        x, cb_w1, cb_b1, cb_w2, cb_b2, cb_w3, cb_b3, cb_g, cb_beta,
        xcA, nullptr, nullptr);
    cell_mlp_kernel<<<NN / 64, 256, SMEM_CELL>>>(
        xcA, cb_w1, cb_b1, cb_w2, cb_b2, cb_w3, cb_b3, cb_g, cb_beta,
        xcB, x, out_x);

    // 3) edge MLP with gathered node features + residual
    edge_mlp_kernel<<<NE / 64, 256, SMEM_EDGE>>>(
        ea, xcB, snd, rcv,
        eb_w1, eb_b1, eb_w2, eb_b2, eb_w3, eb_b3, eb_g, eb_beta,
        out_e);
}

// round 3
// speedup vs baseline: 2.3983x; 2.3983x over previous
#include <cuda_runtime.h>
#include <cuda_bf16.h>
#include <math.h>
#include <stdint.h>

#define NN 200000
#define NE 400000

// ---------------- scratch (static device memory) -----------------------------
__device__ float g_agg[(size_t)NN * 64];
__device__ float g_xcA[(size_t)NN * 128];
__device__ float g_xcB[(size_t)NN * 128];
// transposed + hi/lo-split weights: layout [n=128][K] row-major
__device__ __nv_bfloat16 g_c1h[192 * 128], g_c1l[192 * 128];
__device__ __nv_bfloat16 g_c2h[128 * 128], g_c2l[128 * 128];
__device__ __nv_bfloat16 g_c3h[128 * 128], g_c3l[128 * 128];
__device__ __nv_bfloat16 g_e1h[384 * 128], g_e1l[384 * 128];
__device__ __nv_bfloat16 g_e2h[128 * 128], g_e2l[128 * 128];
__device__ __nv_bfloat16 g_e3h[128 * 128], g_e3l[128 * 128];

// ---------------- smem map (relative to 1024-aligned base) -------------------
#define SM_A0H 0
#define SM_A0L 16384
#define SM_A1H 32768
#define SM_A1L 49152
#define SM_BH  65536
#define SM_BL  81920
#define SM_LN  65536            /* float2 part[2][128], reuses B region */
#define SM_SIDX 98304           /* edge: 256 ints */
#define SMEM_ALLOC (98304 + 1024 + 1024)

static __device__ __forceinline__ uint32_t smem_u32(const void* p) {
    uint32_t a;
    asm("{ .reg .u64 t; cvta.to.shared.u64 t, %1; cvt.u32.u64 %0, t; }" : "=r"(a) : "l"(p));
    return a;
}
static __device__ __forceinline__ uint32_t swz(uint32_t o) { return o ^ ((o >> 3) & 0x70); }
static __device__ __forceinline__ float4 ld4(const float* p) { return *reinterpret_cast<const float4*>(p); }

static __device__ __forceinline__ void ldsm4(uint32_t r[4], uint32_t addr) {
    asm volatile("ldmatrix.sync.aligned.m8n8.x4.shared.b16 {%0,%1,%2,%3}, [%4];"
                 : "=r"(r[0]), "=r"(r[1]), "=r"(r[2]), "=r"(r[3]) : "r"(addr));
}
static __device__ __forceinline__ void mma_bf16(float c[4], const uint32_t a[4], const uint32_t b[2]) {
    asm volatile(
        "mma.sync.aligned.m16n8k16.row.col.f32.bf16.bf16.f32 "
        "{%0,%1,%2,%3}, {%4,%5,%6,%7}, {%8,%9}, {%0,%1,%2,%3};"
        : "+f"(c[0]), "+f"(c[1]), "+f"(c[2]), "+f"(c[3])
        : "r"(a[0]), "r"(a[1]), "r"(a[2]), "r"(a[3]), "r"(b[0]), "r"(b[1]));
}

// ---------------- tile loaders (256 threads) ---------------------------------
// B chunk: global [128][K] bf16 (hi/lo) -> smem [128 n][64 k] SW128
static __device__ __forceinline__ void load_b_chunk(
    char* smA, const __nv_bfloat16* __restrict__ Bh, const __nv_bfloat16* __restrict__ Bl, int K, int c)
{
    int t = threadIdx.x;
    int kq = (t & 15) * 4;          // bf16 col
    int rb = t >> 4;                // 0..15
#pragma unroll
    for (int p = 0; p < 8; p++) {
        int n = p * 16 + rb;
        size_t gi = (size_t)n * K + c * 64 + kq;
        uint2 vh = *reinterpret_cast<const uint2*>(Bh + gi);
        uint2 vl = *reinterpret_cast<const uint2*>(Bl + gi);
        uint32_t off = swz((uint32_t)(n * 128 + kq * 2));
        *reinterpret_cast<uint2*>(smA + SM_BH + off) = vh;
        *reinterpret_cast<uint2*>(smA + SM_BL + off) = vl;
    }
}

// A chunk: fp32 rows -> hi/lo bf16 smem [128][64] SW128 (into A0)
template <typename F>
static __device__ __forceinline__ void load_a_chunk(char* smA, F rowptr)
{
    int t = threadIdx.x;
    int kq = (t & 15) * 4;
    int rb = t >> 4;
#pragma unroll
    for (int p = 0; p < 8; p++) {
        int r = p * 16 + rb;
        const float* rp = rowptr(r);
        float4 v = rp ? ld4(rp + kq) : make_float4(0.f, 0.f, 0.f, 0.f);
        __nv_bfloat162 h01 = __floats2bfloat162_rn(v.x, v.y);
        __nv_bfloat162 h23 = __floats2bfloat162_rn(v.z, v.w);
        float2 f01 = __bfloat1622float2(h01);
        float2 f23 = __bfloat1622float2(h23);
        __nv_bfloat162 l01 = __floats2bfloat162_rn(v.x - f01.x, v.y - f01.y);
        __nv_bfloat162 l23 = __floats2bfloat162_rn(v.z - f23.x, v.w - f23.y);
        uint32_t off = swz((uint32_t)(r * 128 + kq * 2));
        uint2 hh, ll;
        hh.x = *reinterpret_cast<uint32_t*>(&h01);
        hh.y = *reinterpret_cast<uint32_t*>(&h23);
        ll.x = *reinterpret_cast<uint32_t*>(&l01);
        ll.y = *reinterpret_cast<uint32_t*>(&l23);
        *reinterpret_cast<uint2*>(smA + SM_A0H + off) = hh;
        *reinterpret_cast<uint2*>(smA + SM_A0L + off) = ll;
    }
}

// ---------------- warp GEMM over one 64-k chunk ------------------------------
// acc[mf][nf][4]: warp tile 32(m) x 64(n); mf: 16-row frag; nf: 8-col frag
static __device__ __forceinline__ void compute_chunk(
    uint32_t sb, int offAh, int offAl, float acc[2][8][4], int wm, int wn, int lane)
{
#pragma unroll
    for (int kk = 0; kk < 4; kk++) {
        uint32_t ah[2][4], al[2][4];
        int rowA = wm * 32 + (lane & 15);
        int kbA = kk * 32 + (lane >> 4) * 16;
#pragma unroll
        for (int mf = 0; mf < 2; mf++) {
            uint32_t o = swz((uint32_t)((rowA + mf * 16) * 128 + kbA));
            ldsm4(ah[mf], sb + offAh + o);
            ldsm4(al[mf], sb + offAl + o);
        }
        int rowB = wn * 64 + ((lane >> 4) & 1) * 8 + (lane & 7);
        int kbB = kk * 32 + ((lane >> 3) & 1) * 16;
#pragma unroll
        for (int ng = 0; ng < 4; ng++) {
            uint32_t bh[4], bl[4];
            uint32_t o = swz((uint32_t)((rowB + ng * 16) * 128 + kbB));
            ldsm4(bh, sb + SM_BH + o);
            ldsm4(bl, sb + SM_BL + o);
#pragma unroll
            for (int mf = 0; mf < 2; mf++) {
                mma_bf16(acc[mf][ng * 2],     ah[mf], bh);
                mma_bf16(acc[mf][ng * 2 + 1], ah[mf], bh + 2);
                mma_bf16(acc[mf][ng * 2],     al[mf], bh);
                mma_bf16(acc[mf][ng * 2 + 1], al[mf], bh + 2);
                mma_bf16(acc[mf][ng * 2],     ah[mf], bl);
                mma_bf16(acc[mf][ng * 2 + 1], ah[mf], bl + 2);
            }
        }
    }
}

static __device__ __forceinline__ void zero_acc(float acc[2][8][4]) {
#pragma unroll
    for (int mf = 0; mf < 2; mf++)
#pragma unroll
        for (int nf = 0; nf < 8; nf++)
#pragma unroll
            for (int j = 0; j < 4; j++) acc[mf][nf][j] = 0.f;
}

// ---------------- epilogues --------------------------------------------------
// bias + SiLU, split hi/lo, store to A0 (cols 0-63) / A1 (cols 64-127)
static __device__ __forceinline__ void epi_silu(
    char* smA, float acc[2][8][4], const float* __restrict__ bias, int wm, int wn, int lane)
{
    __syncthreads();
    int oh = wn ? SM_A1H : SM_A0H;
    int ol = wn ? SM_A1L : SM_A0L;
#pragma unroll
    for (int mf = 0; mf < 2; mf++)
#pragma unroll
        for (int nf = 0; nf < 8; nf++) {
            int colin = nf * 8 + (lane & 3) * 2;      // within 64-col half
            int col = wn * 64 + colin;
            float b0 = __ldg(bias + col), b1 = __ldg(bias + col + 1);
#pragma unroll
            for (int h = 0; h < 2; h++) {
                float v0 = acc[mf][nf][2 * h]     + b0;
                float v1 = acc[mf][nf][2 * h + 1] + b1;
                v0 = v0 / (1.f + __expf(-v0));
                v1 = v1 / (1.f + __expf(-v1));
                __nv_bfloat162 hh = __floats2bfloat162_rn(v0, v1);
                float2 hf = __bfloat1622float2(hh);
                __nv_bfloat162 ll = __floats2bfloat162_rn(v0 - hf.x, v1 - hf.y);
                int row = wm * 32 + mf * 16 + (lane >> 2) + h * 8;
                uint32_t off = swz((uint32_t)(row * 128 + colin * 2));
                *reinterpret_cast<uint32_t*>(smA + oh + off) = *reinterpret_cast<uint32_t*>(&hh);
                *reinterpret_cast<uint32_t*>(smA + ol + off) = *reinterpret_cast<uint32_t*>(&ll);
            }
        }
}

// bias + LayerNorm + writes (out1 raw LN; out2 = resid + LN)
static __device__ __forceinline__ void epi_ln(
    char* smA, float acc[2][8][4],
    const float* __restrict__ b3, const float* __restrict__ gam, const float* __restrict__ bet,
    float* __restrict__ out1, const float* __restrict__ resid, float* __restrict__ out2,
    long row0, long limit, int wm, int wn, int lane)
{
    __syncthreads();
    float2* part = reinterpret_cast<float2*>(smA + SM_LN);   // [2][128]
    float ps[2][2], ps2[2][2];
#pragma unroll
    for (int mf = 0; mf < 2; mf++)
#pragma unroll
        for (int h = 0; h < 2; h++) { ps[mf][h] = 0.f; ps2[mf][h] = 0.f; }
#pragma unroll
    for (int mf = 0; mf < 2; mf++)
#pragma unroll
        for (int nf = 0; nf < 8; nf++) {
            int col = wn * 64 + nf * 8 + (lane & 3) * 2;
            float b0 = __ldg(b3 + col), b1 = __ldg(b3 + col + 1);
#pragma unroll
            for (int h = 0; h < 2; h++) {
                float v0 = acc[mf][nf][2 * h] + b0;     acc[mf][nf][2 * h] = v0;
                float v1 = acc[mf][nf][2 * h + 1] + b1; acc[mf][nf][2 * h + 1] = v1;
                ps[mf][h] += v0 + v1;
                ps2[mf][h] += v0 * v0 + v1 * v1;
            }
        }
#pragma unroll
    for (int mf = 0; mf < 2; mf++)
#pragma unroll
        for (int h = 0; h < 2; h++) {
            ps[mf][h]  += __shfl_xor_sync(0xffffffffu, ps[mf][h], 1);
            ps2[mf][h] += __shfl_xor_sync(0xffffffffu, ps2[mf][h], 1);
            ps[mf][h]  += __shfl_xor_sync(0xffffffffu, ps[mf][h], 2);
            ps2[mf][h] += __shfl_xor_sync(0xffffffffu, ps2[mf][h], 2);
        }
    if ((lane & 3) == 0) {
#pragma unroll
        for (int mf = 0; mf < 2; mf++)
#pragma unroll
            for (int h = 0; h < 2; h++) {
                int row = wm * 32 + mf * 16 + (lane >> 2) + h * 8;
                part[wn * 128 + row] = make_float2(ps[mf][h], ps2[mf][h]);
            }
    }
    __syncthreads();
    float mn[2][2], rs[2][2];
#pragma unroll
    for (int mf = 0; mf < 2; mf++)
#pragma unroll
        for (int h = 0; h < 2; h++) {
            int row = wm * 32 + mf * 16 + (lane >> 2) + h * 8;
            float2 o = part[(1 - wn) * 128 + row];
            float s = ps[mf][h] + o.x, s2 = ps2[mf][h] + o.y;
            float mean = s * (1.f / 128.f);
            float var = s2 * (1.f / 128.f) - mean * mean;
            mn[mf][h] = mean;
            rs[mf][h] = rsqrtf(var + 1e-5f);
        }
#pragma unroll
    for (int mf = 0; mf < 2; mf++)
#pragma unroll
        for (int nf = 0; nf < 8; nf++) {
            int col = wn * 64 + nf * 8 + (lane & 3) * 2;
            float g0 = __ldg(gam + col), g1 = __ldg(gam + col + 1);
            float e0 = __ldg(bet + col), e1 = __ldg(bet + col + 1);
#pragma unroll
            for (int h = 0; h < 2; h++) {
                int row = wm * 32 + mf * 16 + (lane >> 2) + h * 8;
                long gr = row0 + row;
                if (gr >= limit) continue;
                float o0 = (acc[mf][nf][2 * h]     - mn[mf][h]) * rs[mf][h] * g0 + e0;
                float o1 = (acc[mf][nf][2 * h + 1] - mn[mf][h]) * rs[mf][h] * g1 + e1;
                if (out1) *reinterpret_cast<float2*>(out1 + gr * 128 + col) = make_float2(o0, o1);
                if (out2) {
                    float2 rv = *reinterpret_cast<const float2*>(resid + gr * 128 + col);
                    *reinterpret_cast<float2*>(out2 + gr * 128 + col) = make_float2(o0 + rv.x, o1 + rv.y);
                }
            }
        }
}

// layers 2 & 3 + final LN (shared by cell/edge)
static __device__ __forceinline__ void mlp_rest(
    char* smA, uint32_t sb, float acc[2][8][4],
    const __nv_bfloat16* w2h, const __nv_bfloat16* w2l,
    const __nv_bfloat16* w3h, const __nv_bfloat16* w3l,
    const float* b1, const float* b2, const float* b3,
    const float* gam, const float* bet,
    float* out1, const float* resid, float* out2, long row0, long limit,
    int wm, int wn, int lane)
{
    epi_silu(smA, acc, b1, wm, wn, lane);
    zero_acc(acc);
#pragma unroll 1
    for (int c = 0; c < 2; c++) {
        __syncthreads();
        load_b_chunk(smA, w2h, w2l, 128, c);
        __syncthreads();
        compute_chunk(sb, c ? SM_A1H : SM_A0H, c ? SM_A1L : SM_A0L, acc, wm, wn, lane);
    }
    epi_silu(smA, acc, b2, wm, wn, lane);
    zero_acc(acc);
#pragma unroll 1
    for (int c = 0; c < 2; c++) {
        __syncthreads();
        load_b_chunk(smA, w3h, w3l, 128, c);
        __syncthreads();
        compute_chunk(sb, c ? SM_A1H : SM_A0H, c ? SM_A1L : SM_A0L, acc, wm, wn, lane);
    }
    epi_ln(smA, acc, b3, gam, bet, out1, resid, out2, row0, limit, wm, wn, lane);
}

// ---------------- cell (node) MLP kernel -------------------------------------
__global__ void __launch_bounds__(256, 2) cell_kernel(
    const float* __restrict__ xin,
    const float* __restrict__ b1, const float* __restrict__ b2, const float* __restrict__ b3,
    const float* __restrict__ gam, const float* __restrict__ bet,
    float* __restrict__ out1, const float* __restrict__ resid, float* __restrict__ out2)
{
    extern __shared__ char smraw[];
    uint32_t sb0 = smem_u32(smraw);
    uint32_t sb = (sb0 + 1023u) & ~1023u;
    char* smA = smraw + (sb - sb0);
    int tid = threadIdx.x, lane = tid & 31, wid = tid >> 5;
    int wm = wid >> 1, wn = wid & 1;
    long row0 = (long)blockIdx.x * 128;

    float acc[2][8][4];
    zero_acc(acc);

    // layer 1: K = 192 -> chunks {xin[0:64), xin[64:128), agg[0:64)}
#pragma unroll 1
    for (int c = 0; c < 3; c++) {
        __syncthreads();
        load_b_chunk(smA, g_c1h, g_c1l, 192, c);
        if (c < 2) {
            const float* base = xin + c * 64;
            load_a_chunk(smA, [&](int r) -> const float* {
                long gr = row0 + r;
                return gr < NN ? base + gr * 128 : (const float*)nullptr;
            });
        } else {
            load_a_chunk(smA, [&](int r) -> const float* {
                long gr = row0 + r;
                return gr < NN ? g_agg + gr * 64 : (const float*)nullptr;
            });
        }
        __syncthreads();
        compute_chunk(sb, SM_A0H, SM_A0L, acc, wm, wn, lane);
    }
    mlp_rest(smA, sb, acc, g_c2h, g_c2l, g_c3h, g_c3l,
             b1, b2, b3, gam, bet, out1, resid, out2, row0, NN, wm, wn, lane);
}

// ---------------- edge MLP kernel --------------------------------------------
__global__ void __launch_bounds__(256, 2) edge_kernel(
    const float* __restrict__ ea, const float* __restrict__ xc,
    const int* __restrict__ snd, const int* __restrict__ rcv,
    const float* __restrict__ b1, const float* __restrict__ b2, const float* __restrict__ b3,
    const float* __restrict__ gam, const float* __restrict__ bet,
    float* __restrict__ out2)
{
    extern __shared__ char smraw[];
    uint32_t sb0 = smem_u32(smraw);
    uint32_t sb = (sb0 + 1023u) & ~1023u;
    char* smA = smraw + (sb - sb0);
    int tid = threadIdx.x, lane = tid & 31, wid = tid >> 5;
    int wm = wid >> 1, wn = wid & 1;
    long row0 = (long)blockIdx.x * 128;

    int* sidx = reinterpret_cast<int*>(smA + SM_SIDX);
    if (tid < 128) sidx[tid] = snd[row0 + tid];
    else           sidx[tid] = rcv[row0 + tid - 128];

    float acc[2][8][4];
    zero_acc(acc);

    // layer 1: K = 384 -> {ea x2, xc[snd] x2, xc[rcv] x2}
#pragma unroll 1
    for (int c = 0; c < 6; c++) {
        __syncthreads();
        load_b_chunk(smA, g_e1h, g_e1l, 384, c);
        load_a_chunk(smA, [&](int r) -> const float* {
            if (c < 2) return ea + (size_t)(row0 + r) * 128 + c * 64;
            if (c < 4) return xc + (size_t)sidx[r] * 128 + (c - 2) * 64;
            return xc + (size_t)sidx[128 + r] * 128 + (c - 4) * 64;
        });
        __syncthreads();
        compute_chunk(sb, SM_A0H, SM_A0L, acc, wm, wn, lane);
    }
    mlp_rest(smA, sb, acc, g_e2h, g_e2l, g_e3h, g_e3l,
             b1, b2, b3, gam, bet, nullptr, ea, out2, row0, NE, wm, wn, lane);
}

// ---------------- scatter + weight prep --------------------------------------
__global__ void zero_agg_kernel() {
    size_t n = (size_t)NN * 64 / 4;
    for (size_t i = (size_t)blockIdx.x * blockDim.x + threadIdx.x; i < n;
         i += (size_t)gridDim.x * blockDim.x)
        reinterpret_cast<float4*>(g_agg)[i] = make_float4(0.f, 0.f, 0.f, 0.f);
}

__global__ void __launch_bounds__(256) scatter_kernel(
    const float* __restrict__ ea, const int* __restrict__ snd, const int* __restrict__ rcv)
{
    long t = (long)blockIdx.x * blockDim.x + threadIdx.x;
    if (t >= (long)NE * 128) return;
    int e = (int)(t >> 7);
    int c = (int)(t & 127);
    float v = ea[t];
    if (c < 64) atomicAdd(&g_agg[(size_t)rcv[e] * 64 + c], v);
    else        atomicAdd(&g_agg[(size_t)snd[e] * 64 + (c - 64)], v);
}

// W[K][128] fp32 -> Bh/Bl[n][k] bf16 (transposed, hi/lo split)
__global__ void wconv_kernel(const float* __restrict__ W,
                             __nv_bfloat16* __restrict__ Bh, __nv_bfloat16* __restrict__ Bl, int K)
{
    int i = blockIdx.x * blockDim.x + threadIdx.x;
    if (i >= 128 * K) return;
    int n = i / K, k = i - n * K;
    float w = W[(size_t)k * 128 + n];
    __nv_bfloat16 h = __float2bfloat16(w);
    Bh[i] = h;
    Bl[i] = __float2bfloat16(w - __bfloat162float(h));
}

// ---------------- launch -----------------------------------------------------
extern "C" void kernel_launch(void* const* d_in, const int* in_sizes, int n_in,
                              void* d_out, int out_size)
{
    const float* x       = (const float*)d_in[0];
    const float* ea      = (const float*)d_in[1];
    const float* cb_w1   = (const float*)d_in[2];
    const float* cb_b1   = (const float*)d_in[3];
    const float* cb_w2   = (const float*)d_in[4];
    const float* cb_b2   = (const float*)d_in[5];
    const float* cb_w3   = (const float*)d_in[6];
    const float* cb_b3   = (const float*)d_in[7];
    const float* cb_g    = (const float*)d_in[8];
    const float* cb_beta = (const float*)d_in[9];
    const float* eb_w1   = (const float*)d_in[10];
    const float* eb_b1   = (const float*)d_in[11];
    const float* eb_w2   = (const float*)d_in[12];
    const float* eb_b2   = (const float*)d_in[13];
    const float* eb_w3   = (const float*)d_in[14];
    const float* eb_b3   = (const float*)d_in[15];
    const float* eb_g    = (const float*)d_in[16];
    const float* eb_beta = (const float*)d_in[17];
    const int*   ei      = (const int*)d_in[18];
    const int* snd = ei;
    const int* rcv = ei + NE;

    float* out_x = (float*)d_out;
    float* out_e = out_x + (size_t)NN * 128;

    float *xcA, *xcB;
    cudaGetSymbolAddress((void**)&xcA, g_xcA);
    cudaGetSymbolAddress((void**)&xcB, g_xcB);
    __nv_bfloat16 *c1h, *c1l, *c2h, *c2l, *c3h, *c3l, *e1h, *e1l, *e2h, *e2l, *e3h, *e3l;
    cudaGetSymbolAddress((void**)&c1h, g_c1h); cudaGetSymbolAddress((void**)&c1l, g_c1l);
    cudaGetSymbolAddress((void**)&c2h, g_c2h); cudaGetSymbolAddress((void**)&c2l, g_c2l);
    cudaGetSymbolAddress((void**)&c3h, g_c3h); cudaGetSymbolAddress((void**)&c3l, g_c3l);
    cudaGetSymbolAddress((void**)&e1h, g_e1h); cudaGetSymbolAddress((void**)&e1l, g_e1l);
    cudaGetSymbolAddress((void**)&e2h, g_e2h); cudaGetSymbolAddress((void**)&e2l, g_e2l);
    cudaGetSymbolAddress((void**)&e3h, g_e3h); cudaGetSymbolAddress((void**)&e3l, g_e3l);

    cudaFuncSetAttribute(cell_kernel, cudaFuncAttributeMaxDynamicSharedMemorySize, SMEM_ALLOC);
    cudaFuncSetAttribute(edge_kernel, cudaFuncAttributeMaxDynamicSharedMemorySize, SMEM_ALLOC);

    // weight prep (tiny)
    wconv_kernel<<<(128 * 192 + 255) / 256, 256>>>(cb_w1, c1h, c1l, 192);
    wconv_kernel<<<(128 * 128 + 255) / 256, 256>>>(cb_w2, c2h, c2l, 128);
    wconv_kernel<<<(128 * 128 + 255) / 256, 256>>>(cb_w3, c3h, c3l, 128);
    wconv_kernel<<<(128 * 384 + 255) / 256, 256>>>(eb_w1, e1h, e1l, 384);
    wconv_kernel<<<(128 * 128 + 255) / 256, 256>>>(eb_w2, e2h, e2l, 128);
    wconv_kernel<<<(128 * 128 + 255) / 256, 256>>>(eb_w3, e3h, e3l, 128);

    // agg = scatter(edge_attr) — loop-invariant, computed once
    zero_agg_kernel<<<2048, 256>>>();
    scatter_kernel<<<(int)(((long)NE * 128 + 255) / 256), 256>>>(ea, snd, rcv);

    int cell_grid = (NN + 127) / 128;   // 1563
    int edge_grid = NE / 128;           // 3125

    cell_kernel<<<cell_grid, 256, SMEM_ALLOC>>>(
        x, cb_b1, cb_b2, cb_b3, cb_g, cb_beta, xcA, nullptr, nullptr);
    cell_kernel<<<cell_grid, 256, SMEM_ALLOC>>>(
        xcA, cb_b1, cb_b2, cb_b3, cb_g, cb_beta, xcB, x, out_x);
    edge_kernel<<<edge_grid, 256, SMEM_ALLOC>>>(
        ea, xcB, snd, rcv, eb_b1, eb_b2, eb_b3, eb_g, eb_beta, out_e);
}

// round 4
// speedup vs baseline: 2.9411x; 1.2263x over previous
#include <cuda_runtime.h>
#include <cuda_bf16.h>
#include <math.h>
#include <stdint.h>

#define NN 200000
#define NE 400000

// ---------------- scratch (static device memory) -----------------------------
__device__ float g_agg[(size_t)NN * 64];
__device__ __nv_bfloat16 g_xh[(size_t)NN * 128],  g_xl[(size_t)NN * 128];
__device__ __nv_bfloat16 g_x1h[(size_t)NN * 128], g_x1l[(size_t)NN * 128];
__device__ __nv_bfloat16 g_x2h[(size_t)NN * 128], g_x2l[(size_t)NN * 128];
__device__ __nv_bfloat16 g_aggh[(size_t)NN * 64], g_aggl[(size_t)NN * 64];
__device__ __nv_bfloat16 g_eah[(size_t)NE * 128], g_eal[(size_t)NE * 128];
// transposed + hi/lo-split weights: layout [n=128][K] row-major
__device__ __nv_bfloat16 g_c1h[192 * 128], g_c1l[192 * 128];
__device__ __nv_bfloat16 g_c2h[128 * 128], g_c2l[128 * 128];
__device__ __nv_bfloat16 g_c3h[128 * 128], g_c3l[128 * 128];
__device__ __nv_bfloat16 g_e1h[384 * 128], g_e1l[384 * 128];
__device__ __nv_bfloat16 g_e2h[128 * 128], g_e2l[128 * 128];
__device__ __nv_bfloat16 g_e3h[128 * 128], g_e3l[128 * 128];

// ---------------- smem map (relative to 1024-aligned base) -------------------
#define SM_A0H 0
#define SM_A0L 16384
#define SM_A1H 32768
#define SM_A1L 49152
#define SM_BH  65536
#define SM_BL  81920
#define SM_LN  65536            /* float2 part[2][128], reuses B region */
#define SM_SIDX 98304           /* edge: 256 ints */
#define SMEM_ALLOC (98304 + 1024 + 1024)

static __device__ __forceinline__ uint32_t smem_u32(const void* p) {
    uint32_t a;
    asm("{ .reg .u64 t; cvta.to.shared.u64 t, %1; cvt.u32.u64 %0, t; }" : "=r"(a) : "l"(p));
    return a;
}
static __device__ __forceinline__ uint32_t swz(uint32_t o) { return o ^ ((o >> 3) & 0x70); }

static __device__ __forceinline__ void ldsm4(uint32_t r[4], uint32_t addr) {
    asm volatile("ldmatrix.sync.aligned.m8n8.x4.shared.b16 {%0,%1,%2,%3}, [%4];"
                 : "=r"(r[0]), "=r"(r[1]), "=r"(r[2]), "=r"(r[3]) : "r"(addr));
}
static __device__ __forceinline__ void mma_bf16(float c[4], const uint32_t a[4], const uint32_t b[2]) {
    asm volatile(
        "mma.sync.aligned.m16n8k16.row.col.f32.bf16.bf16.f32 "
        "{%0,%1,%2,%3}, {%4,%5,%6,%7}, {%8,%9}, {%0,%1,%2,%3};"
        : "+f"(c[0]), "+f"(c[1]), "+f"(c[2]), "+f"(c[3])
        : "r"(a[0]), "r"(a[1]), "r"(a[2]), "r"(a[3]), "r"(b[0]), "r"(b[1]));
}
static __device__ __forceinline__ void cpa16(uint32_t dst, const void* src, uint32_t sz) {
    asm volatile("cp.async.cg.shared.global [%0], [%1], 16, %2;"
                 :: "r"(dst), "l"(src), "r"(sz) : "memory");
}
static __device__ __forceinline__ void cpa_commit() {
    asm volatile("cp.async.commit_group;" ::: "memory");
}
static __device__ __forceinline__ void cpa_wait0() {
    asm volatile("cp.async.wait_group 0;" ::: "memory");
}

// ---------------- async tile loaders (256 threads) ---------------------------
// B chunk: global [128 n][K] bf16 (hi/lo) -> smem [128 n][64 k] SW128
static __device__ __forceinline__ void loadB_async(
    uint32_t sb, const __nv_bfloat16* __restrict__ Bh, const __nv_bfloat16* __restrict__ Bl,
    int K, int c)
{
    int t = threadIdx.x, seg = t & 7, r0 = t >> 3;
    const __nv_bfloat16* bh = Bh + c * 64 + seg * 8;
    const __nv_bfloat16* bl = Bl + c * 64 + seg * 8;
#pragma unroll
    for (int p = 0; p < 4; p++) {
        int n = p * 32 + r0;
        uint32_t off = swz((uint32_t)(n * 128 + seg * 16));
        cpa16(sb + SM_BH + off, bh + (size_t)n * K, 16u);
        cpa16(sb + SM_BL + off, bl + (size_t)n * K, 16u);
    }
}

// ---------------- warp GEMM over one 64-k chunk ------------------------------
static __device__ __forceinline__ void compute_chunk(
    uint32_t sb, int offAh, int offAl, float acc[2][8][4], int wm, int wn, int lane)
{
#pragma unroll
    for (int kk = 0; kk < 4; kk++) {
        uint32_t ah[2][4], al[2][4];
        int rowA = wm * 32 + (lane & 15);
        int kbA = kk * 32 + (lane >> 4) * 16;
#pragma unroll
        for (int mf = 0; mf < 2; mf++) {
            uint32_t o = swz((uint32_t)((rowA + mf * 16) * 128 + kbA));
            ldsm4(ah[mf], sb + offAh + o);
            ldsm4(al[mf], sb + offAl + o);
        }
        int rowB = wn * 64 + ((lane >> 4) & 1) * 8 + (lane & 7);
        int kbB = kk * 32 + ((lane >> 3) & 1) * 16;
#pragma unroll
        for (int ng = 0; ng < 4; ng++) {
            uint32_t bh[4], bl[4];
            uint32_t o = swz((uint32_t)((rowB + ng * 16) * 128 + kbB));
            ldsm4(bh, sb + SM_BH + o);
            ldsm4(bl, sb + SM_BL + o);
#pragma unroll
            for (int mf = 0; mf < 2; mf++) {
                mma_bf16(acc[mf][ng * 2],     ah[mf], bh);
                mma_bf16(acc[mf][ng * 2 + 1], ah[mf], bh + 2);
                mma_bf16(acc[mf][ng * 2],     al[mf], bh);
                mma_bf16(acc[mf][ng * 2 + 1], al[mf], bh + 2);
                mma_bf16(acc[mf][ng * 2],     ah[mf], bl);
                mma_bf16(acc[mf][ng * 2 + 1], ah[mf], bl + 2);
            }
        }
    }
}

static __device__ __forceinline__ void zero_acc(float acc[2][8][4]) {
#pragma unroll
    for (int mf = 0; mf < 2; mf++)
#pragma unroll
        for (int nf = 0; nf < 8; nf++)
#pragma unroll
            for (int j = 0; j < 4; j++) acc[mf][nf][j] = 0.f;
}

// ---------------- epilogues --------------------------------------------------
// bias + SiLU, split hi/lo, store to A0 (cols 0-63) / A1 (cols 64-127).
// Caller must __syncthreads() before (compute done) and after (before next read).
static __device__ __forceinline__ void epi_silu(
    char* smA, float acc[2][8][4], const float* __restrict__ bias, int wm, int wn, int lane)
{
    int oh = wn ? SM_A1H : SM_A0H;
    int ol = wn ? SM_A1L : SM_A0L;
#pragma unroll
    for (int mf = 0; mf < 2; mf++)
#pragma unroll
        for (int nf = 0; nf < 8; nf++) {
            int colin = nf * 8 + (lane & 3) * 2;      // within 64-col half
            int col = wn * 64 + colin;
            float b0 = __ldg(bias + col), b1 = __ldg(bias + col + 1);
#pragma unroll
            for (int h = 0; h < 2; h++) {
                float v0 = acc[mf][nf][2 * h]     + b0;
                float v1 = acc[mf][nf][2 * h + 1] + b1;
                v0 = v0 / (1.f + __expf(-v0));
                v1 = v1 / (1.f + __expf(-v1));
                __nv_bfloat162 hh = __floats2bfloat162_rn(v0, v1);
                float2 hf = __bfloat1622float2(hh);
                __nv_bfloat162 ll = __floats2bfloat162_rn(v0 - hf.x, v1 - hf.y);
                int row = wm * 32 + mf * 16 + (lane >> 2) + h * 8;
                uint32_t off = swz((uint32_t)(row * 128 + colin * 2));
                *reinterpret_cast<uint32_t*>(smA + oh + off) = *reinterpret_cast<uint32_t*>(&hh);
                *reinterpret_cast<uint32_t*>(smA + ol + off) = *reinterpret_cast<uint32_t*>(&ll);
            }
        }
}

// bias + LayerNorm; optional bf16 hi/lo output (outh/outl) and fp32 resid+LN (outf).
// Caller must __syncthreads() before (B region reused as scratch).
static __device__ __forceinline__ void epi_ln(
    char* smA, float acc[2][8][4],
    const float* __restrict__ b3, const float* __restrict__ gam, const float* __restrict__ bet,
    __nv_bfloat16* __restrict__ outh, __nv_bfloat16* __restrict__ outl,
    const float* __restrict__ resid, float* __restrict__ outf,
    long row0, long limit, int wm, int wn, int lane)
{
    float2* part = reinterpret_cast<float2*>(smA + SM_LN);   // [2][128]
    float ps[2][2], ps2[2][2];
#pragma unroll
    for (int mf = 0; mf < 2; mf++)
#pragma unroll
        for (int h = 0; h < 2; h++) { ps[mf][h] = 0.f; ps2[mf][h] = 0.f; }
#pragma unroll
    for (int mf = 0; mf < 2; mf++)
#pragma unroll
        for (int nf = 0; nf < 8; nf++) {
            int col = wn * 64 + nf * 8 + (lane & 3) * 2;
            float b0 = __ldg(b3 + col), b1 = __ldg(b3 + col + 1);
#pragma unroll
            for (int h = 0; h < 2; h++) {
                float v0 = acc[mf][nf][2 * h] + b0;     acc[mf][nf][2 * h] = v0;
                float v1 = acc[mf][nf][2 * h + 1] + b1; acc[mf][nf][2 * h + 1] = v1;
                ps[mf][h] += v0 + v1;
                ps2[mf][h] += v0 * v0 + v1 * v1;
            }
        }
#pragma unroll
    for (int mf = 0; mf < 2; mf++)
#pragma unroll
        for (int h = 0; h < 2; h++) {
            ps[mf][h]  += __shfl_xor_sync(0xffffffffu, ps[mf][h], 1);
            ps2[mf][h] += __shfl_xor_sync(0xffffffffu, ps2[mf][h], 1);
            ps[mf][h]  += __shfl_xor_sync(0xffffffffu, ps[mf][h], 2);
            ps2[mf][h] += __shfl_xor_sync(0xffffffffu, ps2[mf][h], 2);
        }
    if ((lane & 3) == 0) {
#pragma unroll
        for (int mf = 0; mf < 2; mf++)
#pragma unroll
            for (int h = 0; h < 2; h++) {
                int row = wm * 32 + mf * 16 + (lane >> 2) + h * 8;
                part[wn * 128 + row] = make_float2(ps[mf][h], ps2[mf][h]);
            }
    }
    __syncthreads();
    float mn[2][2], rs[2][2];
#pragma unroll
    for (int mf = 0; mf < 2; mf++)
#pragma unroll
        for (int h = 0; h < 2; h++) {
            int row = wm * 32 + mf * 16 + (lane >> 2) + h * 8;
            float2 o = part[(1 - wn) * 128 + row];
            float s = ps[mf][h] + o.x, s2 = ps2[mf][h] + o.y;
            float mean = s * (1.f / 128.f);
            float var = s2 * (1.f / 128.f) - mean * mean;
            mn[mf][h] = mean;
            rs[mf][h] = rsqrtf(var + 1e-5f);
        }
#pragma unroll
    for (int mf = 0; mf < 2; mf++)
#pragma unroll
        for (int nf = 0; nf < 8; nf++) {
            int col = wn * 64 + nf * 8 + (lane & 3) * 2;
            float g0 = __ldg(gam + col), g1 = __ldg(gam + col + 1);
            float e0 = __ldg(bet + col), e1 = __ldg(bet + col + 1);
#pragma unroll
            for (int h = 0; h < 2; h++) {
                int row = wm * 32 + mf * 16 + (lane >> 2) + h * 8;
                long gr = row0 + row;
                if (gr >= limit) continue;
                float o0 = (acc[mf][nf][2 * h]     - mn[mf][h]) * rs[mf][h] * g0 + e0;
                float o1 = (acc[mf][nf][2 * h + 1] - mn[mf][h]) * rs[mf][h] * g1 + e1;
                if (outh) {
                    __nv_bfloat162 hh = __floats2bfloat162_rn(o0, o1);
                    float2 hf = __bfloat1622float2(hh);
                    __nv_bfloat162 ll = __floats2bfloat162_rn(o0 - hf.x, o1 - hf.y);
                    *reinterpret_cast<__nv_bfloat162*>(outh + gr * 128 + col) = hh;
                    *reinterpret_cast<__nv_bfloat162*>(outl + gr * 128 + col) = ll;
                }
                if (outf) {
                    float2 rv = *reinterpret_cast<const float2*>(resid + gr * 128 + col);
                    *reinterpret_cast<float2*>(outf + gr * 128 + col) = make_float2(o0 + rv.x, o1 + rv.y);
                }
            }
        }
}

// layers 2 & 3 (B prefetched across layer boundaries, overlapping epilogues)
static __device__ __forceinline__ void run_l23(
    char* smA, uint32_t sb, float acc[2][8][4],
    const __nv_bfloat16* w2h, const __nv_bfloat16* w2l,
    const __nv_bfloat16* w3h, const __nv_bfloat16* w3l,
    const float* b1, const float* b2, int wm, int wn, int lane)
{
    // entering: last L1 compute just finished (no barrier yet)
    __syncthreads();
    loadB_async(sb, w2h, w2l, 128, 0); cpa_commit();   // overlaps epi_silu
    epi_silu(smA, acc, b1, wm, wn, lane);
    zero_acc(acc);
    cpa_wait0(); __syncthreads();
    compute_chunk(sb, SM_A0H, SM_A0L, acc, wm, wn, lane);
    __syncthreads();
    loadB_async(sb, w2h, w2l, 128, 1); cpa_commit();
    cpa_wait0(); __syncthreads();
    compute_chunk(sb, SM_A1H, SM_A1L, acc, wm, wn, lane);
    __syncthreads();
    loadB_async(sb, w3h, w3l, 128, 0); cpa_commit();   // overlaps epi_silu
    epi_silu(smA, acc, b2, wm, wn, lane);
    zero_acc(acc);
    cpa_wait0(); __syncthreads();
    compute_chunk(sb, SM_A0H, SM_A0L, acc, wm, wn, lane);
    __syncthreads();
    loadB_async(sb, w3h, w3l, 128, 1); cpa_commit();
    cpa_wait0(); __syncthreads();
    compute_chunk(sb, SM_A1H, SM_A1L, acc, wm, wn, lane);
    __syncthreads();
    // caller: epi_ln
}

// ---------------- cell (node) MLP kernel -------------------------------------
__global__ void __launch_bounds__(256, 2) cell_kernel(
    const __nv_bfloat16* __restrict__ xh, const __nv_bfloat16* __restrict__ xl,
    const float* __restrict__ b1, const float* __restrict__ b2, const float* __restrict__ b3,
    const float* __restrict__ gam, const float* __restrict__ bet,
    __nv_bfloat16* __restrict__ outh, __nv_bfloat16* __restrict__ outl,
    const float* __restrict__ resid, float* __restrict__ outf)
{
    extern __shared__ char smraw[];
    uint32_t sb0 = smem_u32(smraw);
    uint32_t sb = (sb0 + 1023u) & ~1023u;
    char* smA = smraw + (sb - sb0);
    int tid = threadIdx.x, lane = tid & 31, wid = tid >> 5;
    int wm = wid >> 1, wn = wid & 1;
    long row0 = (long)blockIdx.x * 128;

    auto issueA = [&](int c, int par) {
        uint32_t oh = par ? SM_A1H : SM_A0H, ol = par ? SM_A1L : SM_A0L;
        int seg = tid & 7, r0 = tid >> 3;
#pragma unroll
        for (int p = 0; p < 4; p++) {
            int r = p * 32 + r0;
            long gr = row0 + r;
            bool v = gr < NN;
            const __nv_bfloat16 *ph, *pl;
            if (c < 2) {
                size_t o = v ? ((size_t)gr * 128 + (size_t)c * 64 + seg * 8) : 0;
                ph = xh + o; pl = xl + o;
            } else {
                size_t o = v ? ((size_t)gr * 64 + seg * 8) : 0;
                ph = g_aggh + o; pl = g_aggl + o;
            }
            uint32_t off = swz((uint32_t)(r * 128 + seg * 16));
            cpa16(sb + oh + off, ph, v ? 16u : 0u);
            cpa16(sb + ol + off, pl, v ? 16u : 0u);
        }
        cpa_commit();
    };

    float acc[2][8][4];
    zero_acc(acc);

    issueA(0, 0);
    loadB_async(sb, g_c1h, g_c1l, 192, 0); cpa_commit();
    cpa_wait0(); __syncthreads();
    issueA(1, 1);                                    // in flight during compute 0
    compute_chunk(sb, SM_A0H, SM_A0L, acc, wm, wn, lane);
    __syncthreads();
    loadB_async(sb, g_c1h, g_c1l, 192, 1); cpa_commit();
    cpa_wait0(); __syncthreads();
    issueA(2, 0);                                    // in flight during compute 1
    compute_chunk(sb, SM_A1H, SM_A1L, acc, wm, wn, lane);
    __syncthreads();
    loadB_async(sb, g_c1h, g_c1l, 192, 2); cpa_commit();
    cpa_wait0(); __syncthreads();
    compute_chunk(sb, SM_A0H, SM_A0L, acc, wm, wn, lane);

    run_l23(smA, sb, acc, g_c2h, g_c2l, g_c3h, g_c3l, b1, b2, wm, wn, lane);
    epi_ln(smA, acc, b3, gam, bet, outh, outl, resid, outf, row0, NN, wm, wn, lane);
}

// ---------------- edge MLP kernel --------------------------------------------
__global__ void __launch_bounds__(256, 2) edge_kernel(
    const __nv_bfloat16* __restrict__ eah, const __nv_bfloat16* __restrict__ eal,
    const __nv_bfloat16* __restrict__ x2h, const __nv_bfloat16* __restrict__ x2l,
    const int* __restrict__ snd, const int* __restrict__ rcv,
    const float* __restrict__ b1, const float* __restrict__ b2, const float* __restrict__ b3,
    const float* __restrict__ gam, const float* __restrict__ bet,
    const float* __restrict__ ea_resid, float* __restrict__ outf)
{
    extern __shared__ char smraw[];
    uint32_t sb0 = smem_u32(smraw);
    uint32_t sb = (sb0 + 1023u) & ~1023u;
    char* smA = smraw + (sb - sb0);
    int tid = threadIdx.x, lane = tid & 31, wid = tid >> 5;
    int wm = wid >> 1, wn = wid & 1;
    long row0 = (long)blockIdx.x * 128;

    int* sidx = reinterpret_cast<int*>(smA + SM_SIDX);
    if (tid < 128) sidx[tid] = snd[row0 + tid];
    else           sidx[tid] = rcv[row0 + tid - 128];

    auto issueA = [&](int c, int par) {
        uint32_t oh = par ? SM_A1H : SM_A0H, ol = par ? SM_A1L : SM_A0L;
        int seg = tid & 7, r0 = tid >> 3;
#pragma unroll
        for (int p = 0; p < 4; p++) {
            int r = p * 32 + r0;
            size_t o;
            const __nv_bfloat16 *ph, *pl;
            if (c < 2) {
                o = (size_t)(row0 + r) * 128 + (size_t)c * 64 + seg * 8;
                ph = eah + o; pl = eal + o;
            } else {
                int node = sidx[(c >= 4 ? 128 : 0) + r];
                o = (size_t)node * 128 + (size_t)(c & 1) * 64 + seg * 8;
                ph = x2h + o; pl = x2l + o;
            }
            uint32_t off = swz((uint32_t)(r * 128 + seg * 16));
            cpa16(sb + oh + off, ph, 16u);
            cpa16(sb + ol + off, pl, 16u);
        }
        cpa_commit();
    };

    float acc[2][8][4];
    zero_acc(acc);

    issueA(0, 0);
    loadB_async(sb, g_e1h, g_e1l, 384, 0); cpa_commit();
    cpa_wait0(); __syncthreads();          // sidx also visible now
    issueA(1, 1);
    compute_chunk(sb, SM_A0H, SM_A0L, acc, wm, wn, lane);
#pragma unroll 1
    for (int c = 1; c <= 4; c++) {
        __syncthreads();
        loadB_async(sb, g_e1h, g_e1l, 384, c); cpa_commit();
        cpa_wait0(); __syncthreads();
        issueA(c + 1, (c + 1) & 1);
        compute_chunk(sb, (c & 1) ? SM_A1H : SM_A0H, (c & 1) ? SM_A1L : SM_A0L, acc, wm, wn, lane);
    }
    __syncthreads();
    loadB_async(sb, g_e1h, g_e1l, 384, 5); cpa_commit();
    cpa_wait0(); __syncthreads();
    compute_chunk(sb, SM_A1H, SM_A1L, acc, wm, wn, lane);

    run_l23(smA, sb, acc, g_e2h, g_e2l, g_e3h, g_e3l, b1, b2, wm, wn, lane);
    epi_ln(smA, acc, b3, gam, bet, nullptr, nullptr, ea_resid, outf, row0, NE, wm, wn, lane);
}

// ---------------- scatter + conversions + weight prep ------------------------
__global__ void zero_agg_kernel() {
    size_t n = (size_t)NN * 64 / 4;
    for (size_t i = (size_t)blockIdx.x * blockDim.x + threadIdx.x; i < n;
         i += (size_t)gridDim.x * blockDim.x)
        reinterpret_cast<float4*>(g_agg)[i] = make_float4(0.f, 0.f, 0.f, 0.f);
}

// scatter + fused ea -> bf16 hi/lo conversion
__global__ void __launch_bounds__(256) scatter_kernel(
    const float* __restrict__ ea, const int* __restrict__ snd, const int* __restrict__ rcv,
    __nv_bfloat16* __restrict__ eah, __nv_bfloat16* __restrict__ eal)
{
    long t = (long)blockIdx.x * blockDim.x + threadIdx.x;
    if (t >= (long)NE * 128) return;
    int e = (int)(t >> 7);
    int c = (int)(t & 127);
    float v = ea[t];
    __nv_bfloat16 h = __float2bfloat16(v);
    eah[t] = h;
    eal[t] = __float2bfloat16(v - __bfloat162float(h));
    if (c < 64) atomicAdd(&g_agg[(size_t)rcv[e] * 64 + c], v);
    else        atomicAdd(&g_agg[(size_t)snd[e] * 64 + (c - 64)], v);
}

// fp32 -> bf16 hi/lo split (pairs)
__global__ void conv_hl_kernel(const float* __restrict__ src,
                               __nv_bfloat16* __restrict__ h, __nv_bfloat16* __restrict__ l, long n2)
{
    long i = (long)blockIdx.x * blockDim.x + threadIdx.x;
    if (i >= n2) return;
    float2 v = reinterpret_cast<const float2*>(src)[i];
    __nv_bfloat162 hh = __floats2bfloat162_rn(v.x, v.y);
    float2 hf = __bfloat1622float2(hh);
    __nv_bfloat162 ll = __floats2bfloat162_rn(v.x - hf.x, v.y - hf.y);
    reinterpret_cast<__nv_bfloat162*>(h)[i] = hh;
    reinterpret_cast<__nv_bfloat162*>(l)[i] = ll;
}

// W[K][128] fp32 -> Bh/Bl[n][k] bf16 (transposed, hi/lo split)
__global__ void wconv_kernel(const float* __restrict__ W,
                             __nv_bfloat16* __restrict__ Bh, __nv_bfloat16* __restrict__ Bl, int K)
{
    int i = blockIdx.x * blockDim.x + threadIdx.x;
    if (i >= 128 * K) return;
    int n = i / K, k = i - n * K;
    float w = W[(size_t)k * 128 + n];
    __nv_bfloat16 h = __float2bfloat16(w);
    Bh[i] = h;
    Bl[i] = __float2bfloat16(w - __bfloat162float(h));
}

// ---------------- launch -----------------------------------------------------
extern "C" void kernel_launch(void* const* d_in, const int* in_sizes, int n_in,
                              void* d_out, int out_size)
{
    const float* x       = (const float*)d_in[0];
    const float* ea      = (const float*)d_in[1];
    const float* cb_w1   = (const float*)d_in[2];
    const float* cb_b1   = (const float*)d_in[3];
    const float* cb_w2   = (const float*)d_in[4];
    const float* cb_b2   = (const float*)d_in[5];
    const float* cb_w3   = (const float*)d_in[6];
    const float* cb_b3   = (const float*)d_in[7];
    const float* cb_g    = (const float*)d_in[8];
    const float* cb_beta = (const float*)d_in[9];
    const float* eb_w1   = (const float*)d_in[10];
    const float* eb_b1   = (const float*)d_in[11];
    const float* eb_w2   = (const float*)d_in[12];
    const float* eb_b2   = (const float*)d_in[13];
    const float* eb_w3   = (const float*)d_in[14];
    const float* eb_b3   = (const float*)d_in[15];
    const float* eb_g    = (const float*)d_in[16];
    const float* eb_beta = (const float*)d_in[17];
    const int*   ei      = (const int*)d_in[18];
    const int* snd = ei;
    const int* rcv = ei + NE;

    float* out_x = (float*)d_out;
    float* out_e = out_x + (size_t)NN * 128;

    float* aggf;
    cudaGetSymbolAddress((void**)&aggf, g_agg);
    __nv_bfloat16 *xh, *xl, *x1h, *x1l, *x2h, *x2l, *aggh, *aggl, *eah, *eal;
    cudaGetSymbolAddress((void**)&xh,  g_xh);  cudaGetSymbolAddress((void**)&xl,  g_xl);
    cudaGetSymbolAddress((void**)&x1h, g_x1h); cudaGetSymbolAddress((void**)&x1l, g_x1l);
    cudaGetSymbolAddress((void**)&x2h, g_x2h); cudaGetSymbolAddress((void**)&x2l, g_x2l);
    cudaGetSymbolAddress((void**)&aggh, g_aggh); cudaGetSymbolAddress((void**)&aggl, g_aggl);
    cudaGetSymbolAddress((void**)&eah, g_eah); cudaGetSymbolAddress((void**)&eal, g_eal);
    __nv_bfloat16 *c1h, *c1l, *c2h, *c2l, *c3h, *c3l, *e1h, *e1l, *e2h, *e2l, *e3h, *e3l;
    cudaGetSymbolAddress((void**)&c1h, g_c1h); cudaGetSymbolAddress((void**)&c1l, g_c1l);
    cudaGetSymbolAddress((void**)&c2h, g_c2h); cudaGetSymbolAddress((void**)&c2l, g_c2l);
    cudaGetSymbolAddress((void**)&c3h, g_c3h); cudaGetSymbolAddress((void**)&c3l, g_c3l);
    cudaGetSymbolAddress((void**)&e1h, g_e1h); cudaGetSymbolAddress((void**)&e1l, g_e1l);
    cudaGetSymbolAddress((void**)&e2h, g_e2h); cudaGetSymbolAddress((void**)&e2l, g_e2l);
    cudaGetSymbolAddress((void**)&e3h, g_e3h); cudaGetSymbolAddress((void**)&e3l, g_e3l);

    cudaFuncSetAttribute(cell_kernel, cudaFuncAttributeMaxDynamicSharedMemorySize, SMEM_ALLOC);
    cudaFuncSetAttribute(edge_kernel, cudaFuncAttributeMaxDynamicSharedMemorySize, SMEM_ALLOC);

    // weight prep (tiny)
    wconv_kernel<<<(128 * 192 + 255) / 256, 256>>>(cb_w1, c1h, c1l, 192);
    wconv_kernel<<<(128 * 128 + 255) / 256, 256>>>(cb_w2, c2h, c2l, 128);
    wconv_kernel<<<(128 * 128 + 255) / 256, 256>>>(cb_w3, c3h, c3l, 128);
    wconv_kernel<<<(128 * 384 + 255) / 256, 256>>>(eb_w1, e1h, e1l, 384);
    wconv_kernel<<<(128 * 128 + 255) / 256, 256>>>(eb_w2, e2h, e2l, 128);
    wconv_kernel<<<(128 * 128 + 255) / 256, 256>>>(eb_w3, e3h, e3l, 128);

    // x -> bf16 hi/lo
    conv_hl_kernel<<<(int)(((long)NN * 64 + 255) / 256), 256>>>(x, xh, xl, (long)NN * 64);

    // agg = scatter(edge_attr), fused ea conversion; then split agg
    zero_agg_kernel<<<2048, 256>>>();
    scatter_kernel<<<(int)(((long)NE * 128 + 255) / 256), 256>>>(ea, snd, rcv, eah, eal);
    conv_hl_kernel<<<(int)(((long)NN * 32 + 255) / 256), 256>>>(aggf, aggh, aggl, (long)NN * 32);

    int cell_grid = (NN + 127) / 128;   // 1563
    int edge_grid = NE / 128;           // 3125

    // round 1: xc1 = MLP([x, agg]) -> bf16 hi/lo only
    cell_kernel<<<cell_grid, 256, SMEM_ALLOC>>>(
        xh, xl, cb_b1, cb_b2, cb_b3, cb_g, cb_beta, x1h, x1l, nullptr, nullptr);
    // round 2: xc2 = MLP([xc1, agg]); out_x = x + xc2; also xc2 as bf16 hi/lo
    cell_kernel<<<cell_grid, 256, SMEM_ALLOC>>>(
        x1h, x1l, cb_b1, cb_b2, cb_b3, cb_g, cb_beta, x2h, x2l, x, out_x);
    // edge: e_new = MLP([ea, xc2[snd], xc2[rcv]]); out_e = ea + e_new
    edge_kernel<<<edge_grid, 256, SMEM_ALLOC>>>(
        eah, eal, x2h, x2l, snd, rcv,
        eb_b1, eb_b2, eb_b3, eb_g, eb_beta, ea, out_e);
}